// round 3
// baseline (speedup 1.0000x reference)
#include <cuda_runtime.h>
#include <math_constants.h>

#define NMAX 4096
#define WARPS_PER_BLOCK 8
#define BLOCK_THREADS (WARPS_PER_BLOCK * 32)
#define FULLMASK 0xffffffffu

// strict-less insert: within a lane, candidate j's arrive in ascending order,
// so strict < keeps the earlier index on exact ties (matches top_k stability).
// Caller guarantees d2v < s3.
#define TRY_INSERT(d2v, jv)                                        \
    do {                                                           \
        if ((d2v) < s1) {                                          \
            s3 = s2; i3 = i2; s2 = s1; i2 = i1;                    \
            if ((d2v) < s0) { s1 = s0; i1 = i0; s0 = (d2v); i0 = (jv); } \
            else            { s1 = (d2v); i1 = (jv); }             \
        } else {                                                   \
            if ((d2v) < s2) { s3 = s2; i3 = i2; s2 = (d2v); i2 = (jv); } \
            else            { s3 = (d2v); i3 = (jv); }             \
        }                                                          \
    } while (0)

// cross-lane merge: interleaved j order between lanes, so equal distances
// must resolve to the smaller index
#define LESSI(da, ja, db, jb) (((da) < (db)) || ((da) == (db) && (ja) < (jb)))
#define MERGE_INSERT(dv, jv)                                       \
    if (LESSI(dv, jv, s3, i3)) {                                   \
        if (LESSI(dv, jv, s1, i1)) {                               \
            s3 = s2; i3 = i2; s2 = s1; i2 = i1;                    \
            if (LESSI(dv, jv, s0, i0)) { s1 = s0; i1 = i0; s0 = (dv); i0 = (jv); } \
            else                       { s1 = (dv); i1 = (jv); }   \
        } else {                                                   \
            if (LESSI(dv, jv, s2, i2)) { s3 = s2; i3 = i2; s2 = (dv); i2 = (jv); } \
            else                       { s3 = (dv); i3 = (jv); }   \
        }                                                          \
    }

__global__ __launch_bounds__(BLOCK_THREADS)
void nn_pool_kernel(const float* __restrict__ obs1,
                    const float* __restrict__ obs2,
                    const float* __restrict__ W,
                    const float* __restrict__ b,
                    float* __restrict__ out,
                    int n)
{
    // SoA: x's and y's separate so one LDS.128 yields 4 consecutive candidates
    __shared__ __align__(16) float sx[NMAX];
    __shared__ __align__(16) float sy[NMAX];

    const int tid = threadIdx.x;

    const float2* __restrict__ gpos = (const float2*)obs2;
    for (int t = tid; t < n; t += BLOCK_THREADS) {
        float2 p = gpos[t];
        sx[t] = p.x;
        sy[t] = p.y;
    }
    __syncthreads();

    const int warp = tid >> 5;
    const int lane = tid & 31;
    const int i = blockIdx.x * WARPS_PER_BLOCK + warp;
    if (i >= n) return;

    const float pix = sx[i];
    const float piy = sy[i];

    float s0 = CUDART_INF_F, s1 = CUDART_INF_F, s2 = CUDART_INF_F, s3 = CUDART_INF_F;
    int   i0 = n, i1 = n, i2 = n, i3 = n;

    // warp-shared prune threshold: T = min over lanes of s3 (>= running
    // global 4th-best, so discarding d2 >= T is exact). Updated only when
    // the slow path fires.
    float T = CUDART_INF_F;

    // hot loop: lane handles 4 consecutive candidates per iter.
    // Slow path entry is a warp-uniform ballot-gated branch.
    const int niter = n >> 7;   // n / 128
    #pragma unroll 4
    for (int t = 0; t < niter; ++t) {
        const int j = 4 * lane + (t << 7);
        float4 xv = *(const float4*)&sx[j];
        float4 yv = *(const float4*)&sy[j];

        float dx0 = xv.x - pix, dy0 = yv.x - piy;
        float dx1 = xv.y - pix, dy1 = yv.y - piy;
        float dx2 = xv.z - pix, dy2 = yv.z - piy;
        float dx3 = xv.w - pix, dy3 = yv.w - piy;

        float d20 = fmaf(dx0, dx0, dy0 * dy0);
        float d21 = fmaf(dx1, dx1, dy1 * dy1);
        float d22 = fmaf(dx2, dx2, dy2 * dy2);
        float d23 = fmaf(dx3, dx3, dy3 * dy3);

        float m = fminf(fminf(d20, d21), fminf(d22, d23));

        unsigned hit = __ballot_sync(FULLMASK, m < T);
        if (hit) {
            // slow path (warp-uniform entry; per-lane predicated inserts)
            if (m < s3) {
                if (d20 < s3 && (j + 0) != i) TRY_INSERT(d20, j + 0);
                if (d21 < s3 && (j + 1) != i) TRY_INSERT(d21, j + 1);
                if (d22 < s3 && (j + 2) != i) TRY_INSERT(d22, j + 2);
                if (d23 < s3 && (j + 3) != i) TRY_INSERT(d23, j + 3);
            }
            // refresh warp-shared threshold (all lanes participate)
            float tm = s3;
            #pragma unroll
            for (int off = 16; off > 0; off >>= 1)
                tm = fminf(tm, __shfl_xor_sync(FULLMASK, tm, off));
            T = tm;
        }
    }

    // generic tail (n not a multiple of 128)
    for (int j = (niter << 7) + lane; j < n; j += 32) {
        float dx = sx[j] - pix;
        float dy = sy[j] - piy;
        float d2 = fmaf(dx, dx, dy * dy);
        if (d2 < s3 && j != i) TRY_INSERT(d2, j);
    }

    // butterfly merge: after 5 steps every lane holds the warp-global top-4
    #pragma unroll
    for (int off = 16; off > 0; off >>= 1) {
        float t0 = __shfl_xor_sync(FULLMASK, s0, off);
        float t1 = __shfl_xor_sync(FULLMASK, s1, off);
        float t2 = __shfl_xor_sync(FULLMASK, s2, off);
        float t3 = __shfl_xor_sync(FULLMASK, s3, off);
        int   u0 = __shfl_xor_sync(FULLMASK, i0, off);
        int   u1 = __shfl_xor_sync(FULLMASK, i1, off);
        int   u2 = __shfl_xor_sync(FULLMASK, i2, off);
        int   u3 = __shfl_xor_sync(FULLMASK, i3, off);
        MERGE_INSERT(t0, u0);
        MERGE_INSERT(t1, u1);
        MERGE_INSERT(t2, u2);
        MERGE_INSERT(t3, u3);
    }

    // epilogue: lane = k*8 + e computes out[i][k*8 + e]
    const int k = lane >> 3;
    const int e = lane & 7;
    int nj = (k == 0) ? i0 : (k == 1) ? i1 : (k == 2) ? i2 : i3;

    const float2* __restrict__ go1 = (const float2*)obs1;
    float pjx = sx[nj];
    float pjy = sy[nj];
    float2 o1j = go1[nj];
    float2 o1i = go1[i];

    float rpx = pjx - pix;
    float rpy = pjy - piy;
    float rvx = (pjx - o1j.x) - (pix - o1i.x);
    float rvy = (pjy - o1j.y) - (piy - o1i.y);

    float acc = b[e];
    acc = fmaf(rpx, W[0 * 8 + e], acc);
    acc = fmaf(rpy, W[1 * 8 + e], acc);
    acc = fmaf(rvx, W[2 * 8 + e], acc);
    acc = fmaf(rvy, W[3 * 8 + e], acc);

    out[i * 32 + lane] = fmaxf(acc, 0.0f);
}

extern "C" void kernel_launch(void* const* d_in, const int* in_sizes, int n_in,
                              void* d_out, int out_size) {
    const float* obs1 = (const float*)d_in[0];  // [N, 2]
    const float* obs2 = (const float*)d_in[1];  // [N, 2]
    const float* W    = (const float*)d_in[2];  // [4, 8]
    const float* b    = (const float*)d_in[3];  // [8]
    float* out = (float*)d_out;                  // [N, 32]

    int n = in_sizes[0] / 2;
    int blocks = (n + WARPS_PER_BLOCK - 1) / WARPS_PER_BLOCK;
    nn_pool_kernel<<<blocks, BLOCK_THREADS>>>(obs1, obs2, W, b, out, n);
}